// round 12
// baseline (speedup 1.0000x reference)
#include <cuda_runtime.h>
#include <cuda_bf16.h>
#include <cuda_fp16.h>

#define DMODEL 1024
#define NHEADS 16
#define DK     64
#define BATCH  4
#define SEQ    2048
#define MROWS  (BATCH * SEQ)              // 8192
#define SZ     ((size_t)MROWS * DMODEL)   // 8388608 elems
#define WSZ    ((size_t)DMODEL * DMODEL)

typedef unsigned int u32;
typedef unsigned short u16;
typedef __nv_bfloat16 bf16;

// ---------------------------------------------------------------------------
// Device scratch (no allocation allowed)
// ---------------------------------------------------------------------------
__device__ half g_act[6 * SZ];    // [aq_h, aq_l, ak_h, ak_l, av_h, av_l] split-fp16
__device__ half g_prjh[3 * SZ];   // [q, k, v] single fp16
__device__ bf16 g_o[2 * SZ];      // [o_h, o_l] split-bf16
__device__ half g_wh[3 * WSZ];    // [wqT, wkT, wvT] single fp16 (transposed)
__device__ bf16 g_wo[2 * WSZ];    // [wo_h, wo_l] split-bf16 (transposed)

// ---------------------------------------------------------------------------
// PTX helpers (base-ISA only: ldmatrix + mma.sync + cp.async)
// ---------------------------------------------------------------------------
__device__ __forceinline__ u32 cvta_s(const void* p) {
    u32 a; asm("{ .reg .u64 t; cvta.to.shared.u64 t, %1; cvt.u32.u64 %0, t; }"
               : "=r"(a) : "l"(p)); return a;
}
__device__ __forceinline__ void sts128(u32 a, uint4 v) {
    asm volatile("st.shared.v4.b32 [%0], {%1,%2,%3,%4};"
                 :: "r"(a), "r"(v.x), "r"(v.y), "r"(v.z), "r"(v.w) : "memory");
}
__device__ __forceinline__ void cpa16(u32 s, const void* g) {
    asm volatile("{ .reg .u64 gg; cvta.to.global.u64 gg, %1;"
                 "  cp.async.cg.shared.global [%0], [gg], 16; }"
                 :: "r"(s), "l"(g) : "memory");
}
__device__ __forceinline__ void cpcommit() { asm volatile("cp.async.commit_group;" ::: "memory"); }
__device__ __forceinline__ void cpwait1()  { asm volatile("cp.async.wait_group 1;" ::: "memory"); }
__device__ __forceinline__ void cpwait0()  { asm volatile("cp.async.wait_group 0;" ::: "memory"); }

#define SWZ(x) ((x) ^ (((x) >> 3) & 0x70))

__device__ __forceinline__ void ldmx4(u32& r0, u32& r1, u32& r2, u32& r3, u32 a) {
    asm volatile("ldmatrix.sync.aligned.m8n8.x4.shared.b16 {%0,%1,%2,%3}, [%4];"
                 : "=r"(r0), "=r"(r1), "=r"(r2), "=r"(r3) : "r"(a));
}
__device__ __forceinline__ void ldmx4t(u32& r0, u32& r1, u32& r2, u32& r3, u32 a) {
    asm volatile("ldmatrix.sync.aligned.m8n8.x4.trans.shared.b16 {%0,%1,%2,%3}, [%4];"
                 : "=r"(r0), "=r"(r1), "=r"(r2), "=r"(r3) : "r"(a));
}
// bf16 MMA
__device__ __forceinline__ void mma16816(float* d, const u32* a, const u32* b) {
    asm volatile(
        "mma.sync.aligned.m16n8k16.row.col.f32.bf16.bf16.f32 "
        "{%0,%1,%2,%3}, {%4,%5,%6,%7}, {%8,%9}, {%0,%1,%2,%3};"
        : "+f"(d[0]), "+f"(d[1]), "+f"(d[2]), "+f"(d[3])
        : "r"(a[0]), "r"(a[1]), "r"(a[2]), "r"(a[3]), "r"(b[0]), "r"(b[1]));
}
// fp16 MMA
__device__ __forceinline__ void mma16816h(float* d, const u32* a, const u32* b) {
    asm volatile(
        "mma.sync.aligned.m16n8k16.row.col.f32.f16.f16.f32 "
        "{%0,%1,%2,%3}, {%4,%5,%6,%7}, {%8,%9}, {%0,%1,%2,%3};"
        : "+f"(d[0]), "+f"(d[1]), "+f"(d[2]), "+f"(d[3])
        : "r"(a[0]), "r"(a[1]), "r"(a[2]), "r"(a[3]), "r"(b[0]), "r"(b[1]));
}
// bf16 split helpers
__device__ __forceinline__ void split2(float v, u16& h, u16& l) {
    bf16 hb = __float2bfloat16_rn(v);
    h = *reinterpret_cast<u16*>(&hb);
    bf16 lb = __float2bfloat16_rn(v - __bfloat162float(hb));
    l = *reinterpret_cast<u16*>(&lb);
}
__device__ __forceinline__ void split_pack(float x0, float x1, u32& hp, u32& lp) {
    __nv_bfloat162 hh = __floats2bfloat162_rn(x0, x1);
    hp = *reinterpret_cast<u32*>(&hh);
    float r0 = x0 - __bfloat162float(hh.x);
    float r1 = x1 - __bfloat162float(hh.y);
    __nv_bfloat162 ll = __floats2bfloat162_rn(r0, r1);
    lp = *reinterpret_cast<u32*>(&ll);
}
// fp16 helpers (x0 -> low half)
__device__ __forceinline__ u32 pack2h(float x0, float x1) {
    __half2 hh = __floats2half2_rn(x0, x1);
    return *reinterpret_cast<u32*>(&hh);
}
__device__ __forceinline__ void split_pack_h(float x0, float x1, u32& hp, u32& lp) {
    __half2 hh = __floats2half2_rn(x0, x1);
    hp = *reinterpret_cast<u32*>(&hh);
    float r0 = x0 - __low2float(hh);
    float r1 = x1 - __high2float(hh);
    __half2 ll = __floats2half2_rn(r0, r1);
    lp = *reinterpret_cast<u32*>(&ll);
}

// ---------------------------------------------------------------------------
// Conversion kernels
// ---------------------------------------------------------------------------
// fp32 -> split-fp16 (hi + lo)
__global__ __launch_bounds__(256) void conv_split_h(
    const float* __restrict__ x, half* __restrict__ h, half* __restrict__ l, int n4)
{
    int i = blockIdx.x * 256 + threadIdx.x;
    if (i >= n4) return;
    float4 v = ((const float4*)x)[i];
    float vv[4] = {v.x, v.y, v.z, v.w};
    u32 hp[2], lp[2];
#pragma unroll
    for (int e = 0; e < 2; ++e)
        split_pack_h(vv[2 * e], vv[2 * e + 1], hp[e], lp[e]);
    ((uint2*)h)[i] = make_uint2(hp[0], hp[1]);
    ((uint2*)l)[i] = make_uint2(lp[0], lp[1]);
}

// W[k][n] fp32 -> Wt[n][k] single fp16 (transpose through smem)
__global__ __launch_bounds__(256) void conv_wt_h(
    const float* __restrict__ W, half* __restrict__ T)
{
    __shared__ float ts[32][33];
    int tx = threadIdx.x, ty = threadIdx.y;         // 32 x 8
    int x0 = blockIdx.x * 32, y0 = blockIdx.y * 32; // x: n, y: k
#pragma unroll
    for (int i = 0; i < 4; ++i)
        ts[ty + i * 8][tx] = W[(size_t)(y0 + ty + i * 8) * DMODEL + x0 + tx];
    __syncthreads();
#pragma unroll
    for (int i = 0; i < 4; ++i) {
        int n = x0 + ty + i * 8, k = y0 + tx;
        T[(size_t)n * DMODEL + k] = __float2half_rn(ts[tx][ty + i * 8]);
    }
}

// W[k][n] fp32 -> Wt[n][k] split-bf16 (for Wo)
__global__ __launch_bounds__(256) void conv_wt(
    const float* __restrict__ W, bf16* __restrict__ Th, bf16* __restrict__ Tl)
{
    __shared__ float ts[32][33];
    int tx = threadIdx.x, ty = threadIdx.y;
    int x0 = blockIdx.x * 32, y0 = blockIdx.y * 32;
#pragma unroll
    for (int i = 0; i < 4; ++i)
        ts[ty + i * 8][tx] = W[(size_t)(y0 + ty + i * 8) * DMODEL + x0 + tx];
    __syncthreads();
#pragma unroll
    for (int i = 0; i < 4; ++i) {
        int n = x0 + ty + i * 8, k = y0 + tx;
        u16 h, l; split2(ts[tx][ty + i * 8], h, l);
        Th[(size_t)n * DMODEL + k] = *reinterpret_cast<bf16*>(&h);
        Tl[(size_t)n * DMODEL + k] = *reinterpret_cast<bf16*>(&l);
    }
}

// ---------------------------------------------------------------------------
// 2-product split-A fp16 GEMM (projections): C = (Ah+Al) @ B^T + bias -> fp16
// Block 128x128, K-chunk 64, 8 warps (64x32 warp tile).
// smem: 2 stages x [Ah 16K][Al 16K][B 16K] = 96 KB -> 2 CTAs/SM.
// ---------------------------------------------------------------------------
#define G2_ISSUE(st, k0) do {                                                \
    u32 bs_ = sb + (u32)(st) * 49152u;                                       \
    _Pragma("unroll")                                                        \
    for (int it_ = 0; it_ < 4; ++it_) {                                      \
        int i_ = tid + it_ * 256;                                            \
        int row_ = i_ >> 3, c_ = i_ & 7;                                     \
        u32 so_ = SWZ((u32)(row_ * 128 + c_ * 16));                          \
        size_t ao_ = (size_t)(m0 + row_) * DMODEL + (k0) + c_ * 8;           \
        size_t bo_ = (size_t)(n0 + row_) * DMODEL + (k0) + c_ * 8;           \
        cpa16(bs_ + so_,          Ah + ao_);                                 \
        cpa16(bs_ + 16384u + so_, Al + ao_);                                 \
        cpa16(bs_ + 32768u + so_, Bh + bo_);                                 \
    }                                                                        \
    cpcommit();                                                              \
} while (0)

__global__ __launch_bounds__(256, 2) void gemm2h(
    const half* __restrict__ Ah, const half* __restrict__ Al,
    const half* __restrict__ Bh, const float* __restrict__ bias,
    half* __restrict__ Out)
{
    extern __shared__ char sm[];
    const u32 sb = cvta_s(sm);
    const int tid = threadIdx.x, wid = tid >> 5, lane = tid & 31;
    const int n0 = blockIdx.x * 128, m0 = blockIdx.y * 128;
    const int wm = (wid >> 2) * 64, wn = (wid & 3) * 32;

    float acc[4][4][4];
#pragma unroll
    for (int mi = 0; mi < 4; ++mi)
#pragma unroll
        for (int nt = 0; nt < 4; ++nt)
#pragma unroll
            for (int e = 0; e < 4; ++e) acc[mi][nt][e] = 0.f;

    G2_ISSUE(0, 0);
    for (int kc = 0; kc < 16; ++kc) {
        if (kc < 15) G2_ISSUE((kc + 1) & 1, (kc + 1) * 64);
        if (kc < 15) cpwait1(); else cpwait0();
        __syncthreads();

        const u32 bs = sb + (u32)(kc & 1) * 49152u;
        const u32 sAh = bs, sAl = bs + 16384u, sB = bs + 32768u;

#pragma unroll
        for (int ks = 0; ks < 4; ++ks) {
            u32 ah[4][4], al[4][4];
#pragma unroll
            for (int mi = 0; mi < 4; ++mi) {
                u32 ad = SWZ((u32)((wm + mi * 16 + (lane & 15)) * 128 +
                                   ks * 32 + (lane >> 4) * 16));
                ldmx4(ah[mi][0], ah[mi][1], ah[mi][2], ah[mi][3], sAh + ad);
                ldmx4(al[mi][0], al[mi][1], al[mi][2], al[mi][3], sAl + ad);
            }
            u32 bh[4][2];
#pragma unroll
            for (int nj = 0; nj < 2; ++nj) {
                u32 ad = SWZ((u32)((wn + nj * 16 + (lane & 15)) * 128 +
                                   ks * 32 + (lane >> 4) * 16));
                u32 r0, r1, r2, r3;
                ldmx4(r0, r1, r2, r3, sB + ad);
                bh[2 * nj][0] = r0; bh[2 * nj][1] = r2;
                bh[2 * nj + 1][0] = r1; bh[2 * nj + 1][1] = r3;
            }
#pragma unroll
            for (int mi = 0; mi < 4; ++mi)
#pragma unroll
                for (int nt = 0; nt < 4; ++nt) {
                    mma16816h(acc[mi][nt], ah[mi], bh[nt]);
                    mma16816h(acc[mi][nt], al[mi], bh[nt]);
                }
        }
        __syncthreads();
    }

    const int g = lane >> 2, tq = lane & 3;
#pragma unroll
    for (int mi = 0; mi < 4; ++mi) {
        int row0 = m0 + wm + mi * 16 + g;
#pragma unroll
        for (int nt = 0; nt < 4; ++nt) {
            int col = n0 + wn + nt * 8 + tq * 2;
            float b0 = bias[col], b1 = bias[col + 1];
            *(u32*)(Out + (size_t)row0 * DMODEL + col) =
                pack2h(acc[mi][nt][0] + b0, acc[mi][nt][1] + b1);
            *(u32*)(Out + (size_t)(row0 + 8) * DMODEL + col) =
                pack2h(acc[mi][nt][2] + b0, acc[mi][nt][3] + b1);
        }
    }
}

// ---------------------------------------------------------------------------
// 3-product split-bf16 GEMM (final output): Cf = (Ah+Al) @ (Bh+Bl)^T + bias
// Block 128x128, K-chunk 64, 2 stages x 64 KB = 128 KB smem.
// ---------------------------------------------------------------------------
#define G3_ISSUE(st, k0) do {                                                \
    u32 bs_ = sb + (u32)(st) * 65536u;                                       \
    _Pragma("unroll")                                                        \
    for (int it_ = 0; it_ < 4; ++it_) {                                      \
        int i_ = tid + it_ * 256;                                            \
        int row_ = i_ >> 3, c_ = i_ & 7;                                     \
        u32 so_ = SWZ((u32)(row_ * 128 + c_ * 16));                          \
        size_t ao_ = (size_t)(m0 + row_) * DMODEL + (k0) + c_ * 8;           \
        size_t bo_ = (size_t)(n0 + row_) * DMODEL + (k0) + c_ * 8;           \
        cpa16(bs_ + so_,          Ah + ao_);                                 \
        cpa16(bs_ + 16384u + so_, Al + ao_);                                 \
        cpa16(bs_ + 32768u + so_, Bh + bo_);                                 \
        cpa16(bs_ + 49152u + so_, Bl + bo_);                                 \
    }                                                                        \
    cpcommit();                                                              \
} while (0)

__global__ __launch_bounds__(256, 1) void gemm3(
    const bf16* __restrict__ Ah, const bf16* __restrict__ Al,
    const bf16* __restrict__ Bh, const bf16* __restrict__ Bl,
    const float* __restrict__ bias, float* __restrict__ Cf)
{
    extern __shared__ char sm[];
    const u32 sb = cvta_s(sm);
    const int tid = threadIdx.x, wid = tid >> 5, lane = tid & 31;
    const int n0 = blockIdx.x * 128, m0 = blockIdx.y * 128;
    const int wm = (wid >> 2) * 64, wn = (wid & 3) * 32;

    float acc[4][4][4];
#pragma unroll
    for (int mi = 0; mi < 4; ++mi)
#pragma unroll
        for (int nt = 0; nt < 4; ++nt)
#pragma unroll
            for (int e = 0; e < 4; ++e) acc[mi][nt][e] = 0.f;

    G3_ISSUE(0, 0);
    for (int kc = 0; kc < 16; ++kc) {
        if (kc < 15) G3_ISSUE((kc + 1) & 1, (kc + 1) * 64);
        if (kc < 15) cpwait1(); else cpwait0();
        __syncthreads();

        const u32 bs = sb + (u32)(kc & 1) * 65536u;
        const u32 sAh = bs, sAl = bs + 16384, sBh = bs + 32768, sBl = bs + 49152;

#pragma unroll
        for (int ks = 0; ks < 4; ++ks) {
            u32 ah[4][4], al[4][4];
#pragma unroll
            for (int mi = 0; mi < 4; ++mi) {
                u32 ad = SWZ((u32)((wm + mi * 16 + (lane & 15)) * 128 +
                                   ks * 32 + (lane >> 4) * 16));
                ldmx4(ah[mi][0], ah[mi][1], ah[mi][2], ah[mi][3], sAh + ad);
                ldmx4(al[mi][0], al[mi][1], al[mi][2], al[mi][3], sAl + ad);
            }
            u32 bh[4][2], bl[4][2];
#pragma unroll
            for (int nj = 0; nj < 2; ++nj) {
                u32 ad = SWZ((u32)((wn + nj * 16 + (lane & 15)) * 128 +
                                   ks * 32 + (lane >> 4) * 16));
                u32 r0, r1, r2, r3;
                ldmx4(r0, r1, r2, r3, sBh + ad);
                bh[2 * nj][0] = r0; bh[2 * nj][1] = r2;
                bh[2 * nj + 1][0] = r1; bh[2 * nj + 1][1] = r3;
                ldmx4(r0, r1, r2, r3, sBl + ad);
                bl[2 * nj][0] = r0; bl[2 * nj][1] = r2;
                bl[2 * nj + 1][0] = r1; bl[2 * nj + 1][1] = r3;
            }
#pragma unroll
            for (int mi = 0; mi < 4; ++mi)
#pragma unroll
                for (int nt = 0; nt < 4; ++nt) {
                    mma16816(acc[mi][nt], ah[mi], bh[nt]);
                    mma16816(acc[mi][nt], ah[mi], bl[nt]);
                    mma16816(acc[mi][nt], al[mi], bh[nt]);
                }
        }
        __syncthreads();
    }

    const int g = lane >> 2, tq = lane & 3;
#pragma unroll
    for (int mi = 0; mi < 4; ++mi) {
        int row0 = m0 + wm + mi * 16 + g;
#pragma unroll
        for (int nt = 0; nt < 4; ++nt) {
            int col = n0 + wn + nt * 8 + tq * 2;
            float b0 = bias[col], b1 = bias[col + 1];
            *(float2*)(Cf + (size_t)row0 * DMODEL + col) =
                make_float2(acc[mi][nt][0] + b0, acc[mi][nt][1] + b1);
            *(float2*)(Cf + (size_t)(row0 + 8) * DMODEL + col) =
                make_float2(acc[mi][nt][2] + b0, acc[mi][nt][3] + b1);
        }
    }
}

// ---------------------------------------------------------------------------
// fp16 HMMA flash attention:
//   S  = Q*K         (1 product; Q, K single fp16)
//   PV = Ph*V + Pl*V (2 products; P split-fp16 in regs, V single fp16)
// 128 q rows per CTA (8 warps x 16 rows), 64-row kv tiles, max-free softmax,
// O accumulated fp32 in registers, output split-bf16.
// smem: Q 16K resident + 2 stages x [K 8K][V 8K] = 48 KB -> 2 CTAs/SM.
// ---------------------------------------------------------------------------
#define KV_ISSUE(st, t) do {                                                 \
    u32 bs_ = sb + 16384u + (u32)(st) * 16384u;                              \
    _Pragma("unroll")                                                        \
    for (int it_ = 0; it_ < 2; ++it_) {                                      \
        int i_ = tid + it_ * 256;                                            \
        int row_ = i_ >> 3, c_ = i_ & 7;                                     \
        u32 so_ = SWZ((u32)(row_ * 128 + c_ * 16));                          \
        size_t go_ = base + (size_t)((t) * 64 + row_) * DMODEL + c_ * 8;     \
        cpa16(bs_ + so_,         Kh_ + go_);                                 \
        cpa16(bs_ + 8192u + so_, Vh_ + go_);                                 \
    }                                                                        \
    cpcommit();                                                              \
} while (0)

__global__ __launch_bounds__(256, 2) void flash_h(
    const half* __restrict__ Qh_, const half* __restrict__ Kh_,
    const half* __restrict__ Vh_,
    bf16* __restrict__ Oh_, bf16* __restrict__ Ol_)
{
    extern __shared__ char sm[];
    const u32 sb = cvta_s(sm);
    const u32 sQ = sb;
    const int tid = threadIdx.x, wid = tid >> 5, lane = tid & 31;
    const int b = blockIdx.z, h = blockIdx.y, q0 = blockIdx.x * 128;
    const size_t base = ((size_t)b * SEQ) * DMODEL + (size_t)h * DK;

    // Load Q (128 x 64 fp16) and prefetch first K/V tile
#pragma unroll
    for (int it = 0; it < 4; ++it) {
        int i = tid + it * 256;
        int row = i >> 3, c = i & 7;
        u32 so = SWZ((u32)(row * 128 + c * 16));
        sts128(sQ + so, *(const uint4*)(Qh_ + base + (size_t)(q0 + row) * DMODEL + c * 8));
    }
    KV_ISSUE(0, 0);
    __syncthreads();

    // Preload Q fragments (Q smem stable for whole kernel)
    u32 qh[4][4];
#pragma unroll
    for (int ks = 0; ks < 4; ++ks) {
        u32 ad = SWZ((u32)((wid * 16 + (lane & 15)) * 128 +
                           ks * 32 + (lane >> 4) * 16));
        ldmx4(qh[ks][0], qh[ks][1], qh[ks][2], qh[ks][3], sQ + ad);
    }

    float oc[8][4];
#pragma unroll
    for (int nt = 0; nt < 8; ++nt)
#pragma unroll
        for (int e = 0; e < 4; ++e) oc[nt][e] = 0.f;
    float rs0 = 0.f, rs1 = 0.f;

    for (int t = 0; t < 32; ++t) {
        if (t < 31) KV_ISSUE((t + 1) & 1, t + 1);
        if (t < 31) cpwait1(); else cpwait0();
        __syncthreads();

        const u32 bs = sb + 16384u + (u32)(t & 1) * 16384u;
        const u32 sK = bs, sV = bs + 8192u;

        // ---- S = Q K^T ----
        float sc[8][4];
#pragma unroll
        for (int nt = 0; nt < 8; ++nt)
#pragma unroll
            for (int e = 0; e < 4; ++e) sc[nt][e] = 0.f;

#pragma unroll
        for (int ks = 0; ks < 4; ++ks) {
            u32 kh[8][2];
#pragma unroll
            for (int nj = 0; nj < 4; ++nj) {
                u32 ad = SWZ((u32)((nj * 16 + (lane & 15)) * 128 +
                                   ks * 32 + (lane >> 4) * 16));
                u32 r0, r1, r2, r3;
                ldmx4(r0, r1, r2, r3, sK + ad);
                kh[2 * nj][0] = r0; kh[2 * nj][1] = r2;
                kh[2 * nj + 1][0] = r1; kh[2 * nj + 1][1] = r3;
            }
#pragma unroll
            for (int nt = 0; nt < 8; ++nt)
                mma16816h(sc[nt], qh[ks], kh[nt]);
        }

        // ---- exp (max-free) + row-sum accumulation ----
#pragma unroll
        for (int nt = 0; nt < 8; ++nt) {
#pragma unroll
            for (int e = 0; e < 4; ++e) sc[nt][e] = __expf(sc[nt][e] * 0.125f);
            rs0 += sc[nt][0] + sc[nt][1];
            rs1 += sc[nt][2] + sc[nt][3];
        }

        // ---- O += Ph V + Pl V  (P split-fp16 from S frags; V via trans) ----
#pragma unroll
        for (int ks = 0; ks < 4; ++ks) {
            const int j0 = 2 * ks, j1 = 2 * ks + 1;
            u32 ph[4], pl[4];
            split_pack_h(sc[j0][0], sc[j0][1], ph[0], pl[0]);
            split_pack_h(sc[j0][2], sc[j0][3], ph[1], pl[1]);
            split_pack_h(sc[j1][0], sc[j1][1], ph[2], pl[2]);
            split_pack_h(sc[j1][2], sc[j1][3], ph[3], pl[3]);

            u32 vh[8][2];
#pragma unroll
            for (int dj = 0; dj < 4; ++dj) {
                u32 ad = SWZ((u32)((ks * 16 + (lane & 15)) * 128 +
                                   dj * 32 + (lane >> 4) * 16));
                u32 r0, r1, r2, r3;
                ldmx4t(r0, r1, r2, r3, sV + ad);
                vh[2 * dj][0] = r0; vh[2 * dj][1] = r1;
                vh[2 * dj + 1][0] = r2; vh[2 * dj + 1][1] = r3;
            }
#pragma unroll
            for (int nt = 0; nt < 8; ++nt) {
                mma16816h(oc[nt], ph, vh[nt]);
                mma16816h(oc[nt], pl, vh[nt]);
            }
        }
        __syncthreads();
    }

    // ---- epilogue: row-sum reduce, normalize, split-bf16 store ----
    rs0 += __shfl_xor_sync(0xffffffffu, rs0, 1);
    rs0 += __shfl_xor_sync(0xffffffffu, rs0, 2);
    rs1 += __shfl_xor_sync(0xffffffffu, rs1, 1);
    rs1 += __shfl_xor_sync(0xffffffffu, rs1, 2);
    const float inv0 = 1.f / rs0, inv1 = 1.f / rs1;

    const int g = lane >> 2, tq = lane & 3;
    const int row0 = q0 + wid * 16 + g;
#pragma unroll
    for (int nt = 0; nt < 8; ++nt) {
        int col = nt * 8 + tq * 2;
        u32 hp, lp;
        split_pack(oc[nt][0] * inv0, oc[nt][1] * inv0, hp, lp);
        *(u32*)(Oh_ + base + (size_t)row0 * DMODEL + col) = hp;
        *(u32*)(Ol_ + base + (size_t)row0 * DMODEL + col) = lp;
        split_pack(oc[nt][2] * inv1, oc[nt][3] * inv1, hp, lp);
        *(u32*)(Oh_ + base + (size_t)(row0 + 8) * DMODEL + col) = hp;
        *(u32*)(Ol_ + base + (size_t)(row0 + 8) * DMODEL + col) = lp;
    }
}

// ---------------------------------------------------------------------------
// Launch
// ---------------------------------------------------------------------------
extern "C" void kernel_launch(void* const* d_in, const int* in_sizes, int n_in,
                              void* d_out, int out_size)
{
    const float* query = (const float*)d_in[0];
    const float* key   = (const float*)d_in[1];
    const float* value = (const float*)d_in[2];
    const float* Wq = (const float*)d_in[3];
    const float* bq = (const float*)d_in[4];
    const float* Wk = (const float*)d_in[5];
    const float* bk = (const float*)d_in[6];
    const float* Wv = (const float*)d_in[7];
    const float* bv = (const float*)d_in[8];
    const float* Wo = (const float*)d_in[9];
    const float* bo = (const float*)d_in[10];
    float* out = (float*)d_out;

    half *act, *prjh, *whbuf;
    bf16 *obuf, *wobuf;
    cudaGetSymbolAddress((void**)&act,   g_act);
    cudaGetSymbolAddress((void**)&prjh,  g_prjh);
    cudaGetSymbolAddress((void**)&obuf,  g_o);
    cudaGetSymbolAddress((void**)&whbuf, g_wh);
    cudaGetSymbolAddress((void**)&wobuf, g_wo);

    half *aq_h = act,          *aq_l = act + SZ;
    half *ak_h = act + 2 * SZ, *ak_l = act + 3 * SZ;
    half *av_h = act + 4 * SZ, *av_l = act + 5 * SZ;
    half *q_h = prjh, *k_h = prjh + SZ, *v_h = prjh + 2 * SZ;
    bf16 *o_h = obuf, *o_l = obuf + SZ;
    half *wq_t = whbuf, *wk_t = whbuf + WSZ, *wv_t = whbuf + 2 * WSZ;
    bf16 *wo_h = wobuf, *wo_l = wobuf + WSZ;

    const int n4 = (int)(SZ / 4);
    conv_split_h<<<(n4 + 255) / 256, 256>>>(query, aq_h, aq_l, n4);
    conv_split_h<<<(n4 + 255) / 256, 256>>>(key,   ak_h, ak_l, n4);
    conv_split_h<<<(n4 + 255) / 256, 256>>>(value, av_h, av_l, n4);
    dim3 wtg(32, 32), wtb(32, 8);
    conv_wt_h<<<wtg, wtb>>>(Wq, wq_t);
    conv_wt_h<<<wtg, wtb>>>(Wk, wk_t);
    conv_wt_h<<<wtg, wtb>>>(Wv, wv_t);
    conv_wt<<<wtg, wtb>>>(Wo, wo_h, wo_l);

    dim3 ggrid(DMODEL / 128, MROWS / 128);   // (8, 64)

    const int g2sm = 98304;   // 2 stages x 48 KB -> 2 CTAs/SM
    cudaFuncSetAttribute(gemm2h, cudaFuncAttributeMaxDynamicSharedMemorySize, g2sm);
    gemm2h<<<ggrid, 256, g2sm>>>(aq_h, aq_l, wq_t, bq, q_h);
    gemm2h<<<ggrid, 256, g2sm>>>(ak_h, ak_l, wk_t, bk, k_h);
    gemm2h<<<ggrid, 256, g2sm>>>(av_h, av_l, wv_t, bv, v_h);

    const int fsm = 49152;    // Q 16 KB + 2 stages x 16 KB -> 2 CTAs/SM
    cudaFuncSetAttribute(flash_h, cudaFuncAttributeMaxDynamicSharedMemorySize, fsm);
    dim3 fgrid(SEQ / 128, NHEADS, BATCH);    // (16, 16, 4)
    flash_h<<<fgrid, 256, fsm>>>(q_h, k_h, v_h, o_h, o_l);

    const int g3sm = 131072;  // 2 stages x 64 KB
    cudaFuncSetAttribute(gemm3, cudaFuncAttributeMaxDynamicSharedMemorySize, g3sm);
    gemm3<<<ggrid, 256, g3sm>>>(o_h, o_l, wo_h, wo_l, bo, out);
}

// round 13
// speedup vs baseline: 1.4693x; 1.4693x over previous
#include <cuda_runtime.h>
#include <cuda_bf16.h>
#include <cuda_fp16.h>

#define DMODEL 1024
#define NHEADS 16
#define DK     64
#define BATCH  4
#define SEQ    2048
#define MROWS  (BATCH * SEQ)              // 8192
#define SZ     ((size_t)MROWS * DMODEL)   // 8388608 elems
#define WSZ    ((size_t)DMODEL * DMODEL)

typedef unsigned int u32;
typedef unsigned short u16;
typedef __nv_bfloat16 bf16;

// ---------------------------------------------------------------------------
// Device scratch (no allocation allowed)
// ---------------------------------------------------------------------------
__device__ half g_act[6 * SZ];    // [aq_h, aq_l, ak_h, ak_l, av_h, av_l] split-fp16
__device__ half g_prjh[3 * SZ];   // [q, k, v] single fp16
__device__ bf16 g_o[2 * SZ];      // [o_h, o_l] split-bf16
__device__ half g_wh[3 * WSZ];    // [wqT, wkT, wvT] single fp16 (transposed)
__device__ bf16 g_wo[2 * WSZ];    // [wo_h, wo_l] split-bf16 (transposed)

// ---------------------------------------------------------------------------
// PTX helpers (base-ISA only: ldmatrix + mma.sync + cp.async)
// ---------------------------------------------------------------------------
__device__ __forceinline__ u32 cvta_s(const void* p) {
    u32 a; asm("{ .reg .u64 t; cvta.to.shared.u64 t, %1; cvt.u32.u64 %0, t; }"
               : "=r"(a) : "l"(p)); return a;
}
__device__ __forceinline__ void sts128(u32 a, uint4 v) {
    asm volatile("st.shared.v4.b32 [%0], {%1,%2,%3,%4};"
                 :: "r"(a), "r"(v.x), "r"(v.y), "r"(v.z), "r"(v.w) : "memory");
}
__device__ __forceinline__ void cpa16(u32 s, const void* g) {
    asm volatile("{ .reg .u64 gg; cvta.to.global.u64 gg, %1;"
                 "  cp.async.cg.shared.global [%0], [gg], 16; }"
                 :: "r"(s), "l"(g) : "memory");
}
__device__ __forceinline__ void cpcommit() { asm volatile("cp.async.commit_group;" ::: "memory"); }
__device__ __forceinline__ void cpwait1()  { asm volatile("cp.async.wait_group 1;" ::: "memory"); }
__device__ __forceinline__ void cpwait0()  { asm volatile("cp.async.wait_group 0;" ::: "memory"); }

#define SWZ(x) ((x) ^ (((x) >> 3) & 0x70))

__device__ __forceinline__ void ldmx4(u32& r0, u32& r1, u32& r2, u32& r3, u32 a) {
    asm volatile("ldmatrix.sync.aligned.m8n8.x4.shared.b16 {%0,%1,%2,%3}, [%4];"
                 : "=r"(r0), "=r"(r1), "=r"(r2), "=r"(r3) : "r"(a));
}
__device__ __forceinline__ void ldmx4t(u32& r0, u32& r1, u32& r2, u32& r3, u32 a) {
    asm volatile("ldmatrix.sync.aligned.m8n8.x4.trans.shared.b16 {%0,%1,%2,%3}, [%4];"
                 : "=r"(r0), "=r"(r1), "=r"(r2), "=r"(r3) : "r"(a));
}
// bf16 MMA
__device__ __forceinline__ void mma16816(float* d, const u32* a, const u32* b) {
    asm volatile(
        "mma.sync.aligned.m16n8k16.row.col.f32.bf16.bf16.f32 "
        "{%0,%1,%2,%3}, {%4,%5,%6,%7}, {%8,%9}, {%0,%1,%2,%3};"
        : "+f"(d[0]), "+f"(d[1]), "+f"(d[2]), "+f"(d[3])
        : "r"(a[0]), "r"(a[1]), "r"(a[2]), "r"(a[3]), "r"(b[0]), "r"(b[1]));
}
// fp16 MMA
__device__ __forceinline__ void mma16816h(float* d, const u32* a, const u32* b) {
    asm volatile(
        "mma.sync.aligned.m16n8k16.row.col.f32.f16.f16.f32 "
        "{%0,%1,%2,%3}, {%4,%5,%6,%7}, {%8,%9}, {%0,%1,%2,%3};"
        : "+f"(d[0]), "+f"(d[1]), "+f"(d[2]), "+f"(d[3])
        : "r"(a[0]), "r"(a[1]), "r"(a[2]), "r"(a[3]), "r"(b[0]), "r"(b[1]));
}
// bf16 split helpers
__device__ __forceinline__ void split2(float v, u16& h, u16& l) {
    bf16 hb = __float2bfloat16_rn(v);
    h = *reinterpret_cast<u16*>(&hb);
    bf16 lb = __float2bfloat16_rn(v - __bfloat162float(hb));
    l = *reinterpret_cast<u16*>(&lb);
}
__device__ __forceinline__ void split_pack(float x0, float x1, u32& hp, u32& lp) {
    __nv_bfloat162 hh = __floats2bfloat162_rn(x0, x1);
    hp = *reinterpret_cast<u32*>(&hh);
    float r0 = x0 - __bfloat162float(hh.x);
    float r1 = x1 - __bfloat162float(hh.y);
    __nv_bfloat162 ll = __floats2bfloat162_rn(r0, r1);
    lp = *reinterpret_cast<u32*>(&ll);
}
// fp16 helpers (x0 -> low half)
__device__ __forceinline__ u32 pack2h(float x0, float x1) {
    __half2 hh = __floats2half2_rn(x0, x1);
    return *reinterpret_cast<u32*>(&hh);
}
__device__ __forceinline__ void split_pack_h(float x0, float x1, u32& hp, u32& lp) {
    __half2 hh = __floats2half2_rn(x0, x1);
    hp = *reinterpret_cast<u32*>(&hh);
    float r0 = x0 - __low2float(hh);
    float r1 = x1 - __high2float(hh);
    __half2 ll = __floats2half2_rn(r0, r1);
    lp = *reinterpret_cast<u32*>(&ll);
}

// ---------------------------------------------------------------------------
// Conversion kernels
// ---------------------------------------------------------------------------
// fp32 -> split-fp16 (hi + lo)
__global__ __launch_bounds__(256) void conv_split_h(
    const float* __restrict__ x, half* __restrict__ h, half* __restrict__ l, int n4)
{
    int i = blockIdx.x * 256 + threadIdx.x;
    if (i >= n4) return;
    float4 v = ((const float4*)x)[i];
    float vv[4] = {v.x, v.y, v.z, v.w};
    u32 hp[2], lp[2];
#pragma unroll
    for (int e = 0; e < 2; ++e)
        split_pack_h(vv[2 * e], vv[2 * e + 1], hp[e], lp[e]);
    ((uint2*)h)[i] = make_uint2(hp[0], hp[1]);
    ((uint2*)l)[i] = make_uint2(lp[0], lp[1]);
}

// W[k][n] fp32 -> Wt[n][k] single fp16 (transpose through smem)
__global__ __launch_bounds__(256) void conv_wt_h(
    const float* __restrict__ W, half* __restrict__ T)
{
    __shared__ float ts[32][33];
    int tx = threadIdx.x, ty = threadIdx.y;         // 32 x 8
    int x0 = blockIdx.x * 32, y0 = blockIdx.y * 32; // x: n, y: k
#pragma unroll
    for (int i = 0; i < 4; ++i)
        ts[ty + i * 8][tx] = W[(size_t)(y0 + ty + i * 8) * DMODEL + x0 + tx];
    __syncthreads();
#pragma unroll
    for (int i = 0; i < 4; ++i) {
        int n = x0 + ty + i * 8, k = y0 + tx;
        T[(size_t)n * DMODEL + k] = __float2half_rn(ts[tx][ty + i * 8]);
    }
}

// W[k][n] fp32 -> Wt[n][k] split-bf16 (for Wo)
__global__ __launch_bounds__(256) void conv_wt(
    const float* __restrict__ W, bf16* __restrict__ Th, bf16* __restrict__ Tl)
{
    __shared__ float ts[32][33];
    int tx = threadIdx.x, ty = threadIdx.y;
    int x0 = blockIdx.x * 32, y0 = blockIdx.y * 32;
#pragma unroll
    for (int i = 0; i < 4; ++i)
        ts[ty + i * 8][tx] = W[(size_t)(y0 + ty + i * 8) * DMODEL + x0 + tx];
    __syncthreads();
#pragma unroll
    for (int i = 0; i < 4; ++i) {
        int n = x0 + ty + i * 8, k = y0 + tx;
        u16 h, l; split2(ts[tx][ty + i * 8], h, l);
        Th[(size_t)n * DMODEL + k] = *reinterpret_cast<bf16*>(&h);
        Tl[(size_t)n * DMODEL + k] = *reinterpret_cast<bf16*>(&l);
    }
}

// ---------------------------------------------------------------------------
// 2-product split-A fp16 GEMM (projections): C = (Ah+Al) @ B^T + bias -> fp16
// Block 128x128, K-chunk 64, 8 warps (64x32 warp tile).
// smem: 2 stages x [Ah 16K][Al 16K][B 16K] = 96 KB.
// NOTE: occupancy 1 — forcing 2 CTAs/SM caps regs at 128 and spills the
// 64-float accumulator (round-12 regression: 1040 -> 1228 us).
// ---------------------------------------------------------------------------
#define G2_ISSUE(st, k0) do {                                                \
    u32 bs_ = sb + (u32)(st) * 49152u;                                       \
    _Pragma("unroll")                                                        \
    for (int it_ = 0; it_ < 4; ++it_) {                                      \
        int i_ = tid + it_ * 256;                                            \
        int row_ = i_ >> 3, c_ = i_ & 7;                                     \
        u32 so_ = SWZ((u32)(row_ * 128 + c_ * 16));                          \
        size_t ao_ = (size_t)(m0 + row_) * DMODEL + (k0) + c_ * 8;           \
        size_t bo_ = (size_t)(n0 + row_) * DMODEL + (k0) + c_ * 8;           \
        cpa16(bs_ + so_,          Ah + ao_);                                 \
        cpa16(bs_ + 16384u + so_, Al + ao_);                                 \
        cpa16(bs_ + 32768u + so_, Bh + bo_);                                 \
    }                                                                        \
    cpcommit();                                                              \
} while (0)

__global__ __launch_bounds__(256, 1) void gemm2h(
    const half* __restrict__ Ah, const half* __restrict__ Al,
    const half* __restrict__ Bh, const float* __restrict__ bias,
    half* __restrict__ Out)
{
    extern __shared__ char sm[];
    const u32 sb = cvta_s(sm);
    const int tid = threadIdx.x, wid = tid >> 5, lane = tid & 31;
    const int n0 = blockIdx.x * 128, m0 = blockIdx.y * 128;
    const int wm = (wid >> 2) * 64, wn = (wid & 3) * 32;

    float acc[4][4][4];
#pragma unroll
    for (int mi = 0; mi < 4; ++mi)
#pragma unroll
        for (int nt = 0; nt < 4; ++nt)
#pragma unroll
            for (int e = 0; e < 4; ++e) acc[mi][nt][e] = 0.f;

    G2_ISSUE(0, 0);
    for (int kc = 0; kc < 16; ++kc) {
        if (kc < 15) G2_ISSUE((kc + 1) & 1, (kc + 1) * 64);
        if (kc < 15) cpwait1(); else cpwait0();
        __syncthreads();

        const u32 bs = sb + (u32)(kc & 1) * 49152u;
        const u32 sAh = bs, sAl = bs + 16384u, sB = bs + 32768u;

#pragma unroll
        for (int ks = 0; ks < 4; ++ks) {
            u32 ah[4][4], al[4][4];
#pragma unroll
            for (int mi = 0; mi < 4; ++mi) {
                u32 ad = SWZ((u32)((wm + mi * 16 + (lane & 15)) * 128 +
                                   ks * 32 + (lane >> 4) * 16));
                ldmx4(ah[mi][0], ah[mi][1], ah[mi][2], ah[mi][3], sAh + ad);
                ldmx4(al[mi][0], al[mi][1], al[mi][2], al[mi][3], sAl + ad);
            }
            u32 bh[4][2];
#pragma unroll
            for (int nj = 0; nj < 2; ++nj) {
                u32 ad = SWZ((u32)((wn + nj * 16 + (lane & 15)) * 128 +
                                   ks * 32 + (lane >> 4) * 16));
                u32 r0, r1, r2, r3;
                ldmx4(r0, r1, r2, r3, sB + ad);
                bh[2 * nj][0] = r0; bh[2 * nj][1] = r2;
                bh[2 * nj + 1][0] = r1; bh[2 * nj + 1][1] = r3;
            }
#pragma unroll
            for (int mi = 0; mi < 4; ++mi)
#pragma unroll
                for (int nt = 0; nt < 4; ++nt) {
                    mma16816h(acc[mi][nt], ah[mi], bh[nt]);
                    mma16816h(acc[mi][nt], al[mi], bh[nt]);
                }
        }
        __syncthreads();
    }

    const int g = lane >> 2, tq = lane & 3;
#pragma unroll
    for (int mi = 0; mi < 4; ++mi) {
        int row0 = m0 + wm + mi * 16 + g;
#pragma unroll
        for (int nt = 0; nt < 4; ++nt) {
            int col = n0 + wn + nt * 8 + tq * 2;
            float b0 = bias[col], b1 = bias[col + 1];
            *(u32*)(Out + (size_t)row0 * DMODEL + col) =
                pack2h(acc[mi][nt][0] + b0, acc[mi][nt][1] + b1);
            *(u32*)(Out + (size_t)(row0 + 8) * DMODEL + col) =
                pack2h(acc[mi][nt][2] + b0, acc[mi][nt][3] + b1);
        }
    }
}

// ---------------------------------------------------------------------------
// 3-product split-bf16 GEMM (final output): Cf = (Ah+Al) @ (Bh+Bl)^T + bias
// Block 128x128, K-chunk 64, 2 stages x 64 KB = 128 KB smem.
// ---------------------------------------------------------------------------
#define G3_ISSUE(st, k0) do {                                                \
    u32 bs_ = sb + (u32)(st) * 65536u;                                       \
    _Pragma("unroll")                                                        \
    for (int it_ = 0; it_ < 4; ++it_) {                                      \
        int i_ = tid + it_ * 256;                                            \
        int row_ = i_ >> 3, c_ = i_ & 7;                                     \
        u32 so_ = SWZ((u32)(row_ * 128 + c_ * 16));                          \
        size_t ao_ = (size_t)(m0 + row_) * DMODEL + (k0) + c_ * 8;           \
        size_t bo_ = (size_t)(n0 + row_) * DMODEL + (k0) + c_ * 8;           \
        cpa16(bs_ + so_,          Ah + ao_);                                 \
        cpa16(bs_ + 16384u + so_, Al + ao_);                                 \
        cpa16(bs_ + 32768u + so_, Bh + bo_);                                 \
        cpa16(bs_ + 49152u + so_, Bl + bo_);                                 \
    }                                                                        \
    cpcommit();                                                              \
} while (0)

__global__ __launch_bounds__(256, 1) void gemm3(
    const bf16* __restrict__ Ah, const bf16* __restrict__ Al,
    const bf16* __restrict__ Bh, const bf16* __restrict__ Bl,
    const float* __restrict__ bias, float* __restrict__ Cf)
{
    extern __shared__ char sm[];
    const u32 sb = cvta_s(sm);
    const int tid = threadIdx.x, wid = tid >> 5, lane = tid & 31;
    const int n0 = blockIdx.x * 128, m0 = blockIdx.y * 128;
    const int wm = (wid >> 2) * 64, wn = (wid & 3) * 32;

    float acc[4][4][4];
#pragma unroll
    for (int mi = 0; mi < 4; ++mi)
#pragma unroll
        for (int nt = 0; nt < 4; ++nt)
#pragma unroll
            for (int e = 0; e < 4; ++e) acc[mi][nt][e] = 0.f;

    G3_ISSUE(0, 0);
    for (int kc = 0; kc < 16; ++kc) {
        if (kc < 15) G3_ISSUE((kc + 1) & 1, (kc + 1) * 64);
        if (kc < 15) cpwait1(); else cpwait0();
        __syncthreads();

        const u32 bs = sb + (u32)(kc & 1) * 65536u;
        const u32 sAh = bs, sAl = bs + 16384, sBh = bs + 32768, sBl = bs + 49152;

#pragma unroll
        for (int ks = 0; ks < 4; ++ks) {
            u32 ah[4][4], al[4][4];
#pragma unroll
            for (int mi = 0; mi < 4; ++mi) {
                u32 ad = SWZ((u32)((wm + mi * 16 + (lane & 15)) * 128 +
                                   ks * 32 + (lane >> 4) * 16));
                ldmx4(ah[mi][0], ah[mi][1], ah[mi][2], ah[mi][3], sAh + ad);
                ldmx4(al[mi][0], al[mi][1], al[mi][2], al[mi][3], sAl + ad);
            }
            u32 bh[4][2], bl[4][2];
#pragma unroll
            for (int nj = 0; nj < 2; ++nj) {
                u32 ad = SWZ((u32)((wn + nj * 16 + (lane & 15)) * 128 +
                                   ks * 32 + (lane >> 4) * 16));
                u32 r0, r1, r2, r3;
                ldmx4(r0, r1, r2, r3, sBh + ad);
                bh[2 * nj][0] = r0; bh[2 * nj][1] = r2;
                bh[2 * nj + 1][0] = r1; bh[2 * nj + 1][1] = r3;
                ldmx4(r0, r1, r2, r3, sBl + ad);
                bl[2 * nj][0] = r0; bl[2 * nj][1] = r2;
                bl[2 * nj + 1][0] = r1; bl[2 * nj + 1][1] = r3;
            }
#pragma unroll
            for (int mi = 0; mi < 4; ++mi)
#pragma unroll
                for (int nt = 0; nt < 4; ++nt) {
                    mma16816(acc[mi][nt], ah[mi], bh[nt]);
                    mma16816(acc[mi][nt], ah[mi], bl[nt]);
                    mma16816(acc[mi][nt], al[mi], bh[nt]);
                }
        }
        __syncthreads();
    }

    const int g = lane >> 2, tq = lane & 3;
#pragma unroll
    for (int mi = 0; mi < 4; ++mi) {
        int row0 = m0 + wm + mi * 16 + g;
#pragma unroll
        for (int nt = 0; nt < 4; ++nt) {
            int col = n0 + wn + nt * 8 + tq * 2;
            float b0 = bias[col], b1 = bias[col + 1];
            *(float2*)(Cf + (size_t)row0 * DMODEL + col) =
                make_float2(acc[mi][nt][0] + b0, acc[mi][nt][1] + b1);
            *(float2*)(Cf + (size_t)(row0 + 8) * DMODEL + col) =
                make_float2(acc[mi][nt][2] + b0, acc[mi][nt][3] + b1);
        }
    }
}

// ---------------------------------------------------------------------------
// fp16 HMMA flash attention:
//   S  = Q*K         (1 product; Q, K single fp16)
//   PV = Ph*V + Pl*V (2 products; P split-fp16 in regs, V single fp16)
// 128 q rows per CTA (8 warps x 16 rows), 64-row kv tiles, max-free softmax,
// O accumulated fp32 in registers, output split-bf16.
// smem: Q 16K resident + 2 stages x [K 8K][V 8K] = 48 KB -> 2 CTAs/SM.
// ---------------------------------------------------------------------------
#define KV_ISSUE(st, t) do {                                                 \
    u32 bs_ = sb + 16384u + (u32)(st) * 16384u;                              \
    _Pragma("unroll")                                                        \
    for (int it_ = 0; it_ < 2; ++it_) {                                      \
        int i_ = tid + it_ * 256;                                            \
        int row_ = i_ >> 3, c_ = i_ & 7;                                     \
        u32 so_ = SWZ((u32)(row_ * 128 + c_ * 16));                          \
        size_t go_ = base + (size_t)((t) * 64 + row_) * DMODEL + c_ * 8;     \
        cpa16(bs_ + so_,         Kh_ + go_);                                 \
        cpa16(bs_ + 8192u + so_, Vh_ + go_);                                 \
    }                                                                        \
    cpcommit();                                                              \
} while (0)

__global__ __launch_bounds__(256, 2) void flash_h(
    const half* __restrict__ Qh_, const half* __restrict__ Kh_,
    const half* __restrict__ Vh_,
    bf16* __restrict__ Oh_, bf16* __restrict__ Ol_)
{
    extern __shared__ char sm[];
    const u32 sb = cvta_s(sm);
    const u32 sQ = sb;
    const int tid = threadIdx.x, wid = tid >> 5, lane = tid & 31;
    const int b = blockIdx.z, h = blockIdx.y, q0 = blockIdx.x * 128;
    const size_t base = ((size_t)b * SEQ) * DMODEL + (size_t)h * DK;

    // Load Q (128 x 64 fp16) and prefetch first K/V tile
#pragma unroll
    for (int it = 0; it < 4; ++it) {
        int i = tid + it * 256;
        int row = i >> 3, c = i & 7;
        u32 so = SWZ((u32)(row * 128 + c * 16));
        sts128(sQ + so, *(const uint4*)(Qh_ + base + (size_t)(q0 + row) * DMODEL + c * 8));
    }
    KV_ISSUE(0, 0);
    __syncthreads();

    // Preload Q fragments (Q smem stable for whole kernel)
    u32 qh[4][4];
#pragma unroll
    for (int ks = 0; ks < 4; ++ks) {
        u32 ad = SWZ((u32)((wid * 16 + (lane & 15)) * 128 +
                           ks * 32 + (lane >> 4) * 16));
        ldmx4(qh[ks][0], qh[ks][1], qh[ks][2], qh[ks][3], sQ + ad);
    }

    float oc[8][4];
#pragma unroll
    for (int nt = 0; nt < 8; ++nt)
#pragma unroll
        for (int e = 0; e < 4; ++e) oc[nt][e] = 0.f;
    float rs0 = 0.f, rs1 = 0.f;

    for (int t = 0; t < 32; ++t) {
        if (t < 31) KV_ISSUE((t + 1) & 1, t + 1);
        if (t < 31) cpwait1(); else cpwait0();
        __syncthreads();

        const u32 bs = sb + 16384u + (u32)(t & 1) * 16384u;
        const u32 sK = bs, sV = bs + 8192u;

        // ---- S = Q K^T ----
        float sc[8][4];
#pragma unroll
        for (int nt = 0; nt < 8; ++nt)
#pragma unroll
            for (int e = 0; e < 4; ++e) sc[nt][e] = 0.f;

#pragma unroll
        for (int ks = 0; ks < 4; ++ks) {
            u32 kh[8][2];
#pragma unroll
            for (int nj = 0; nj < 4; ++nj) {
                u32 ad = SWZ((u32)((nj * 16 + (lane & 15)) * 128 +
                                   ks * 32 + (lane >> 4) * 16));
                u32 r0, r1, r2, r3;
                ldmx4(r0, r1, r2, r3, sK + ad);
                kh[2 * nj][0] = r0; kh[2 * nj][1] = r2;
                kh[2 * nj + 1][0] = r1; kh[2 * nj + 1][1] = r3;
            }
#pragma unroll
            for (int nt = 0; nt < 8; ++nt)
                mma16816h(sc[nt], qh[ks], kh[nt]);
        }

        // ---- exp (max-free) + row-sum accumulation ----
#pragma unroll
        for (int nt = 0; nt < 8; ++nt) {
#pragma unroll
            for (int e = 0; e < 4; ++e) sc[nt][e] = __expf(sc[nt][e] * 0.125f);
            rs0 += sc[nt][0] + sc[nt][1];
            rs1 += sc[nt][2] + sc[nt][3];
        }

        // ---- O += Ph V + Pl V  (P split-fp16 from S frags; V via trans) ----
#pragma unroll
        for (int ks = 0; ks < 4; ++ks) {
            const int j0 = 2 * ks, j1 = 2 * ks + 1;
            u32 ph[4], pl[4];
            split_pack_h(sc[j0][0], sc[j0][1], ph[0], pl[0]);
            split_pack_h(sc[j0][2], sc[j0][3], ph[1], pl[1]);
            split_pack_h(sc[j1][0], sc[j1][1], ph[2], pl[2]);
            split_pack_h(sc[j1][2], sc[j1][3], ph[3], pl[3]);

            u32 vh[8][2];
#pragma unroll
            for (int dj = 0; dj < 4; ++dj) {
                u32 ad = SWZ((u32)((ks * 16 + (lane & 15)) * 128 +
                                   dj * 32 + (lane >> 4) * 16));
                u32 r0, r1, r2, r3;
                ldmx4t(r0, r1, r2, r3, sV + ad);
                vh[2 * dj][0] = r0; vh[2 * dj][1] = r1;
                vh[2 * dj + 1][0] = r2; vh[2 * dj + 1][1] = r3;
            }
#pragma unroll
            for (int nt = 0; nt < 8; ++nt) {
                mma16816h(oc[nt], ph, vh[nt]);
                mma16816h(oc[nt], pl, vh[nt]);
            }
        }
        __syncthreads();
    }

    // ---- epilogue: row-sum reduce, normalize, split-bf16 store ----
    rs0 += __shfl_xor_sync(0xffffffffu, rs0, 1);
    rs0 += __shfl_xor_sync(0xffffffffu, rs0, 2);
    rs1 += __shfl_xor_sync(0xffffffffu, rs1, 1);
    rs1 += __shfl_xor_sync(0xffffffffu, rs1, 2);
    const float inv0 = 1.f / rs0, inv1 = 1.f / rs1;

    const int g = lane >> 2, tq = lane & 3;
    const int row0 = q0 + wid * 16 + g;
#pragma unroll
    for (int nt = 0; nt < 8; ++nt) {
        int col = nt * 8 + tq * 2;
        u32 hp, lp;
        split_pack(oc[nt][0] * inv0, oc[nt][1] * inv0, hp, lp);
        *(u32*)(Oh_ + base + (size_t)row0 * DMODEL + col) = hp;
        *(u32*)(Ol_ + base + (size_t)row0 * DMODEL + col) = lp;
        split_pack(oc[nt][2] * inv1, oc[nt][3] * inv1, hp, lp);
        *(u32*)(Oh_ + base + (size_t)(row0 + 8) * DMODEL + col) = hp;
        *(u32*)(Ol_ + base + (size_t)(row0 + 8) * DMODEL + col) = lp;
    }
}

// ---------------------------------------------------------------------------
// Launch
// ---------------------------------------------------------------------------
extern "C" void kernel_launch(void* const* d_in, const int* in_sizes, int n_in,
                              void* d_out, int out_size)
{
    const float* query = (const float*)d_in[0];
    const float* key   = (const float*)d_in[1];
    const float* value = (const float*)d_in[2];
    const float* Wq = (const float*)d_in[3];
    const float* bq = (const float*)d_in[4];
    const float* Wk = (const float*)d_in[5];
    const float* bk = (const float*)d_in[6];
    const float* Wv = (const float*)d_in[7];
    const float* bv = (const float*)d_in[8];
    const float* Wo = (const float*)d_in[9];
    const float* bo = (const float*)d_in[10];
    float* out = (float*)d_out;

    half *act, *prjh, *whbuf;
    bf16 *obuf, *wobuf;
    cudaGetSymbolAddress((void**)&act,   g_act);
    cudaGetSymbolAddress((void**)&prjh,  g_prjh);
    cudaGetSymbolAddress((void**)&obuf,  g_o);
    cudaGetSymbolAddress((void**)&whbuf, g_wh);
    cudaGetSymbolAddress((void**)&wobuf, g_wo);

    half *aq_h = act,          *aq_l = act + SZ;
    half *ak_h = act + 2 * SZ, *ak_l = act + 3 * SZ;
    half *av_h = act + 4 * SZ, *av_l = act + 5 * SZ;
    half *q_h = prjh, *k_h = prjh + SZ, *v_h = prjh + 2 * SZ;
    bf16 *o_h = obuf, *o_l = obuf + SZ;
    half *wq_t = whbuf, *wk_t = whbuf + WSZ, *wv_t = whbuf + 2 * WSZ;
    bf16 *wo_h = wobuf, *wo_l = wobuf + WSZ;

    const int n4 = (int)(SZ / 4);
    conv_split_h<<<(n4 + 255) / 256, 256>>>(query, aq_h, aq_l, n4);
    conv_split_h<<<(n4 + 255) / 256, 256>>>(key,   ak_h, ak_l, n4);
    conv_split_h<<<(n4 + 255) / 256, 256>>>(value, av_h, av_l, n4);
    dim3 wtg(32, 32), wtb(32, 8);
    conv_wt_h<<<wtg, wtb>>>(Wq, wq_t);
    conv_wt_h<<<wtg, wtb>>>(Wk, wk_t);
    conv_wt_h<<<wtg, wtb>>>(Wv, wv_t);
    conv_wt<<<wtg, wtb>>>(Wo, wo_h, wo_l);

    dim3 ggrid(DMODEL / 128, MROWS / 128);   // (8, 64)

    const int g2sm = 98304;   // 2 stages x 48 KB (occupancy 1 — no reg cap)
    cudaFuncSetAttribute(gemm2h, cudaFuncAttributeMaxDynamicSharedMemorySize, g2sm);
    gemm2h<<<ggrid, 256, g2sm>>>(aq_h, aq_l, wq_t, bq, q_h);
    gemm2h<<<ggrid, 256, g2sm>>>(ak_h, ak_l, wk_t, bk, k_h);
    gemm2h<<<ggrid, 256, g2sm>>>(av_h, av_l, wv_t, bv, v_h);

    const int fsm = 49152;    // Q 16 KB + 2 stages x 16 KB -> 2 CTAs/SM
    cudaFuncSetAttribute(flash_h, cudaFuncAttributeMaxDynamicSharedMemorySize, fsm);
    dim3 fgrid(SEQ / 128, NHEADS, BATCH);    // (16, 16, 4)
    flash_h<<<fgrid, 256, fsm>>>(q_h, k_h, v_h, o_h, o_l);

    const int g3sm = 131072;  // 2 stages x 64 KB
    cudaFuncSetAttribute(gemm3, cudaFuncAttributeMaxDynamicSharedMemorySize, g3sm);
    gemm3<<<ggrid, 256, g3sm>>>(o_h, o_l, wo_h, wo_l, bo, out);
}

// round 14
// speedup vs baseline: 1.7122x; 1.1653x over previous
#include <cuda_runtime.h>
#include <cuda_bf16.h>
#include <cuda_fp16.h>

#define DMODEL 1024
#define NHEADS 16
#define DK     64
#define BATCH  4
#define SEQ    2048
#define MROWS  (BATCH * SEQ)              // 8192
#define SZ     ((size_t)MROWS * DMODEL)   // 8388608 elems
#define WSZ    ((size_t)DMODEL * DMODEL)

typedef unsigned int u32;
typedef unsigned short u16;
typedef __nv_bfloat16 bf16;

// ---------------------------------------------------------------------------
// Device scratch (no allocation allowed)
// ---------------------------------------------------------------------------
__device__ half g_act[6 * SZ];    // [aq_h, aq_l, ak_h, ak_l, av_h, av_l] split-fp16
__device__ half g_prjh[3 * SZ];   // [q, k, v] single fp16
__device__ half g_o[2 * SZ];      // [o_h, o_l] split-fp16
__device__ half g_wh[4 * WSZ];    // [wqT, wkT, wvT, woT] single fp16 (transposed)

// ---------------------------------------------------------------------------
// PTX helpers (base-ISA only: ldmatrix + mma.sync + cp.async)
// ---------------------------------------------------------------------------
__device__ __forceinline__ u32 cvta_s(const void* p) {
    u32 a; asm("{ .reg .u64 t; cvta.to.shared.u64 t, %1; cvt.u32.u64 %0, t; }"
               : "=r"(a) : "l"(p)); return a;
}
__device__ __forceinline__ void sts128(u32 a, uint4 v) {
    asm volatile("st.shared.v4.b32 [%0], {%1,%2,%3,%4};"
                 :: "r"(a), "r"(v.x), "r"(v.y), "r"(v.z), "r"(v.w) : "memory");
}
__device__ __forceinline__ void cpa16(u32 s, const void* g) {
    asm volatile("{ .reg .u64 gg; cvta.to.global.u64 gg, %1;"
                 "  cp.async.cg.shared.global [%0], [gg], 16; }"
                 :: "r"(s), "l"(g) : "memory");
}
__device__ __forceinline__ void cpcommit() { asm volatile("cp.async.commit_group;" ::: "memory"); }
__device__ __forceinline__ void cpwait1()  { asm volatile("cp.async.wait_group 1;" ::: "memory"); }
__device__ __forceinline__ void cpwait0()  { asm volatile("cp.async.wait_group 0;" ::: "memory"); }

#define SWZ(x) ((x) ^ (((x) >> 3) & 0x70))

__device__ __forceinline__ void ldmx4(u32& r0, u32& r1, u32& r2, u32& r3, u32 a) {
    asm volatile("ldmatrix.sync.aligned.m8n8.x4.shared.b16 {%0,%1,%2,%3}, [%4];"
                 : "=r"(r0), "=r"(r1), "=r"(r2), "=r"(r3) : "r"(a));
}
__device__ __forceinline__ void ldmx4t(u32& r0, u32& r1, u32& r2, u32& r3, u32 a) {
    asm volatile("ldmatrix.sync.aligned.m8n8.x4.trans.shared.b16 {%0,%1,%2,%3}, [%4];"
                 : "=r"(r0), "=r"(r1), "=r"(r2), "=r"(r3) : "r"(a));
}
// fp16 MMA
__device__ __forceinline__ void mma16816h(float* d, const u32* a, const u32* b) {
    asm volatile(
        "mma.sync.aligned.m16n8k16.row.col.f32.f16.f16.f32 "
        "{%0,%1,%2,%3}, {%4,%5,%6,%7}, {%8,%9}, {%0,%1,%2,%3};"
        : "+f"(d[0]), "+f"(d[1]), "+f"(d[2]), "+f"(d[3])
        : "r"(a[0]), "r"(a[1]), "r"(a[2]), "r"(a[3]), "r"(b[0]), "r"(b[1]));
}
// fp16 helpers (x0 -> low half)
__device__ __forceinline__ u32 pack2h(float x0, float x1) {
    __half2 hh = __floats2half2_rn(x0, x1);
    return *reinterpret_cast<u32*>(&hh);
}
__device__ __forceinline__ void split_pack_h(float x0, float x1, u32& hp, u32& lp) {
    __half2 hh = __floats2half2_rn(x0, x1);
    hp = *reinterpret_cast<u32*>(&hh);
    float r0 = x0 - __low2float(hh);
    float r1 = x1 - __high2float(hh);
    __half2 ll = __floats2half2_rn(r0, r1);
    lp = *reinterpret_cast<u32*>(&ll);
}

// ---------------------------------------------------------------------------
// Conversion kernels
// ---------------------------------------------------------------------------
// fp32 -> split-fp16 (hi + lo)
__global__ __launch_bounds__(256) void conv_split_h(
    const float* __restrict__ x, half* __restrict__ h, half* __restrict__ l, int n4)
{
    int i = blockIdx.x * 256 + threadIdx.x;
    if (i >= n4) return;
    float4 v = ((const float4*)x)[i];
    float vv[4] = {v.x, v.y, v.z, v.w};
    u32 hp[2], lp[2];
#pragma unroll
    for (int e = 0; e < 2; ++e)
        split_pack_h(vv[2 * e], vv[2 * e + 1], hp[e], lp[e]);
    ((uint2*)h)[i] = make_uint2(hp[0], hp[1]);
    ((uint2*)l)[i] = make_uint2(lp[0], lp[1]);
}

// W[k][n] fp32 -> Wt[n][k] single fp16 (transpose through smem)
__global__ __launch_bounds__(256) void conv_wt_h(
    const float* __restrict__ W, half* __restrict__ T)
{
    __shared__ float ts[32][33];
    int tx = threadIdx.x, ty = threadIdx.y;         // 32 x 8
    int x0 = blockIdx.x * 32, y0 = blockIdx.y * 32; // x: n, y: k
#pragma unroll
    for (int i = 0; i < 4; ++i)
        ts[ty + i * 8][tx] = W[(size_t)(y0 + ty + i * 8) * DMODEL + x0 + tx];
    __syncthreads();
#pragma unroll
    for (int i = 0; i < 4; ++i) {
        int n = x0 + ty + i * 8, k = y0 + tx;
        T[(size_t)n * DMODEL + k] = __float2half_rn(ts[tx][ty + i * 8]);
    }
}

// ---------------------------------------------------------------------------
// 2-product split-A fp16 GEMM: C = (Ah+Al) @ B^T + bias
// Output: fp16 (Outh) when Cf==null, else fp32 (Cf).
// Block 128x128, K-chunk 64, 8 warps (64x32 warp tile).
// smem: 2 stages x [Ah 16K][Al 16K][B 16K] = 96 KB.
// Occupancy 1 — forcing 2 CTAs/SM caps regs at 128 and spills the 64-float
// accumulator (round-12 regression: 1040 -> 1228 us).
// ---------------------------------------------------------------------------
#define G2_ISSUE(st, k0) do {                                                \
    u32 bs_ = sb + (u32)(st) * 49152u;                                       \
    _Pragma("unroll")                                                        \
    for (int it_ = 0; it_ < 4; ++it_) {                                      \
        int i_ = tid + it_ * 256;                                            \
        int row_ = i_ >> 3, c_ = i_ & 7;                                     \
        u32 so_ = SWZ((u32)(row_ * 128 + c_ * 16));                          \
        size_t ao_ = (size_t)(m0 + row_) * DMODEL + (k0) + c_ * 8;           \
        size_t bo_ = (size_t)(n0 + row_) * DMODEL + (k0) + c_ * 8;           \
        cpa16(bs_ + so_,          Ah + ao_);                                 \
        cpa16(bs_ + 16384u + so_, Al + ao_);                                 \
        cpa16(bs_ + 32768u + so_, Bh + bo_);                                 \
    }                                                                        \
    cpcommit();                                                              \
} while (0)

__global__ __launch_bounds__(256, 1) void gemm2h(
    const half* __restrict__ Ah, const half* __restrict__ Al,
    const half* __restrict__ Bh, const float* __restrict__ bias,
    half* __restrict__ Outh, float* __restrict__ Cf)
{
    extern __shared__ char sm[];
    const u32 sb = cvta_s(sm);
    const int tid = threadIdx.x, wid = tid >> 5, lane = tid & 31;
    const int n0 = blockIdx.x * 128, m0 = blockIdx.y * 128;
    const int wm = (wid >> 2) * 64, wn = (wid & 3) * 32;

    float acc[4][4][4];
#pragma unroll
    for (int mi = 0; mi < 4; ++mi)
#pragma unroll
        for (int nt = 0; nt < 4; ++nt)
#pragma unroll
            for (int e = 0; e < 4; ++e) acc[mi][nt][e] = 0.f;

    G2_ISSUE(0, 0);
    for (int kc = 0; kc < 16; ++kc) {
        if (kc < 15) G2_ISSUE((kc + 1) & 1, (kc + 1) * 64);
        if (kc < 15) cpwait1(); else cpwait0();
        __syncthreads();

        const u32 bs = sb + (u32)(kc & 1) * 49152u;
        const u32 sAh = bs, sAl = bs + 16384u, sB = bs + 32768u;

#pragma unroll
        for (int ks = 0; ks < 4; ++ks) {
            u32 ah[4][4], al[4][4];
#pragma unroll
            for (int mi = 0; mi < 4; ++mi) {
                u32 ad = SWZ((u32)((wm + mi * 16 + (lane & 15)) * 128 +
                                   ks * 32 + (lane >> 4) * 16));
                ldmx4(ah[mi][0], ah[mi][1], ah[mi][2], ah[mi][3], sAh + ad);
                ldmx4(al[mi][0], al[mi][1], al[mi][2], al[mi][3], sAl + ad);
            }
            u32 bh[4][2];
#pragma unroll
            for (int nj = 0; nj < 2; ++nj) {
                u32 ad = SWZ((u32)((wn + nj * 16 + (lane & 15)) * 128 +
                                   ks * 32 + (lane >> 4) * 16));
                u32 r0, r1, r2, r3;
                ldmx4(r0, r1, r2, r3, sB + ad);
                bh[2 * nj][0] = r0; bh[2 * nj][1] = r2;
                bh[2 * nj + 1][0] = r1; bh[2 * nj + 1][1] = r3;
            }
#pragma unroll
            for (int mi = 0; mi < 4; ++mi)
#pragma unroll
                for (int nt = 0; nt < 4; ++nt) {
                    mma16816h(acc[mi][nt], ah[mi], bh[nt]);
                    mma16816h(acc[mi][nt], al[mi], bh[nt]);
                }
        }
        __syncthreads();
    }

    const int g = lane >> 2, tq = lane & 3;
#pragma unroll
    for (int mi = 0; mi < 4; ++mi) {
        int row0 = m0 + wm + mi * 16 + g;
#pragma unroll
        for (int nt = 0; nt < 4; ++nt) {
            int col = n0 + wn + nt * 8 + tq * 2;
            float b0 = bias[col], b1 = bias[col + 1];
            float v00 = acc[mi][nt][0] + b0, v01 = acc[mi][nt][1] + b1;
            float v10 = acc[mi][nt][2] + b0, v11 = acc[mi][nt][3] + b1;
            if (Cf) {
                *(float2*)(Cf + (size_t)row0 * DMODEL + col) = make_float2(v00, v01);
                *(float2*)(Cf + (size_t)(row0 + 8) * DMODEL + col) = make_float2(v10, v11);
            } else {
                *(u32*)(Outh + (size_t)row0 * DMODEL + col) = pack2h(v00, v01);
                *(u32*)(Outh + (size_t)(row0 + 8) * DMODEL + col) = pack2h(v10, v11);
            }
        }
    }
}

// ---------------------------------------------------------------------------
// fp16 HMMA flash attention:
//   S  = Q*K   (1 product; Q, K single fp16)
//   PV = P*V   (1 product; P single fp16 from regs, V single fp16)
// 128 q rows per CTA (8 warps x 16 rows), 64-row kv tiles, max-free softmax,
// O accumulated fp32 in registers, output split-fp16 (for the final GEMM).
// smem: Q 16K resident + 2 stages x [K 8K][V 8K] = 48 KB -> 2 CTAs/SM.
// ---------------------------------------------------------------------------
#define KV_ISSUE(st, t) do {                                                 \
    u32 bs_ = sb + 16384u + (u32)(st) * 16384u;                              \
    _Pragma("unroll")                                                        \
    for (int it_ = 0; it_ < 2; ++it_) {                                      \
        int i_ = tid + it_ * 256;                                            \
        int row_ = i_ >> 3, c_ = i_ & 7;                                     \
        u32 so_ = SWZ((u32)(row_ * 128 + c_ * 16));                          \
        size_t go_ = base + (size_t)((t) * 64 + row_) * DMODEL + c_ * 8;     \
        cpa16(bs_ + so_,         Kh_ + go_);                                 \
        cpa16(bs_ + 8192u + so_, Vh_ + go_);                                 \
    }                                                                        \
    cpcommit();                                                              \
} while (0)

__global__ __launch_bounds__(256, 2) void flash_h(
    const half* __restrict__ Qh_, const half* __restrict__ Kh_,
    const half* __restrict__ Vh_,
    half* __restrict__ Oh_, half* __restrict__ Ol_)
{
    extern __shared__ char sm[];
    const u32 sb = cvta_s(sm);
    const u32 sQ = sb;
    const int tid = threadIdx.x, wid = tid >> 5, lane = tid & 31;
    const int b = blockIdx.z, h = blockIdx.y, q0 = blockIdx.x * 128;
    const size_t base = ((size_t)b * SEQ) * DMODEL + (size_t)h * DK;

    // Load Q (128 x 64 fp16) and prefetch first K/V tile
#pragma unroll
    for (int it = 0; it < 4; ++it) {
        int i = tid + it * 256;
        int row = i >> 3, c = i & 7;
        u32 so = SWZ((u32)(row * 128 + c * 16));
        sts128(sQ + so, *(const uint4*)(Qh_ + base + (size_t)(q0 + row) * DMODEL + c * 8));
    }
    KV_ISSUE(0, 0);
    __syncthreads();

    // Preload Q fragments (Q smem stable for whole kernel)
    u32 qh[4][4];
#pragma unroll
    for (int ks = 0; ks < 4; ++ks) {
        u32 ad = SWZ((u32)((wid * 16 + (lane & 15)) * 128 +
                           ks * 32 + (lane >> 4) * 16));
        ldmx4(qh[ks][0], qh[ks][1], qh[ks][2], qh[ks][3], sQ + ad);
    }

    float oc[8][4];
#pragma unroll
    for (int nt = 0; nt < 8; ++nt)
#pragma unroll
        for (int e = 0; e < 4; ++e) oc[nt][e] = 0.f;
    float rs0 = 0.f, rs1 = 0.f;

    for (int t = 0; t < 32; ++t) {
        if (t < 31) KV_ISSUE((t + 1) & 1, t + 1);
        if (t < 31) cpwait1(); else cpwait0();
        __syncthreads();

        const u32 bs = sb + 16384u + (u32)(t & 1) * 16384u;
        const u32 sK = bs, sV = bs + 8192u;

        // ---- S = Q K^T ----
        float sc[8][4];
#pragma unroll
        for (int nt = 0; nt < 8; ++nt)
#pragma unroll
            for (int e = 0; e < 4; ++e) sc[nt][e] = 0.f;

#pragma unroll
        for (int ks = 0; ks < 4; ++ks) {
            u32 kh[8][2];
#pragma unroll
            for (int nj = 0; nj < 4; ++nj) {
                u32 ad = SWZ((u32)((nj * 16 + (lane & 15)) * 128 +
                                   ks * 32 + (lane >> 4) * 16));
                u32 r0, r1, r2, r3;
                ldmx4(r0, r1, r2, r3, sK + ad);
                kh[2 * nj][0] = r0; kh[2 * nj][1] = r2;
                kh[2 * nj + 1][0] = r1; kh[2 * nj + 1][1] = r3;
            }
#pragma unroll
            for (int nt = 0; nt < 8; ++nt)
                mma16816h(sc[nt], qh[ks], kh[nt]);
        }

        // ---- exp (max-free) + row-sum accumulation ----
#pragma unroll
        for (int nt = 0; nt < 8; ++nt) {
#pragma unroll
            for (int e = 0; e < 4; ++e) sc[nt][e] = __expf(sc[nt][e] * 0.125f);
            rs0 += sc[nt][0] + sc[nt][1];
            rs1 += sc[nt][2] + sc[nt][3];
        }

        // ---- O += P V  (P single fp16 from S frags; V via ldmatrix.trans) ----
#pragma unroll
        for (int ks = 0; ks < 4; ++ks) {
            const int j0 = 2 * ks, j1 = 2 * ks + 1;
            u32 ph[4];
            ph[0] = pack2h(sc[j0][0], sc[j0][1]);
            ph[1] = pack2h(sc[j0][2], sc[j0][3]);
            ph[2] = pack2h(sc[j1][0], sc[j1][1]);
            ph[3] = pack2h(sc[j1][2], sc[j1][3]);

            u32 vh[8][2];
#pragma unroll
            for (int dj = 0; dj < 4; ++dj) {
                u32 ad = SWZ((u32)((ks * 16 + (lane & 15)) * 128 +
                                   dj * 32 + (lane >> 4) * 16));
                u32 r0, r1, r2, r3;
                ldmx4t(r0, r1, r2, r3, sV + ad);
                vh[2 * dj][0] = r0; vh[2 * dj][1] = r1;
                vh[2 * dj + 1][0] = r2; vh[2 * dj + 1][1] = r3;
            }
#pragma unroll
            for (int nt = 0; nt < 8; ++nt)
                mma16816h(oc[nt], ph, vh[nt]);
        }
        __syncthreads();
    }

    // ---- epilogue: row-sum reduce, normalize, split-fp16 store ----
    rs0 += __shfl_xor_sync(0xffffffffu, rs0, 1);
    rs0 += __shfl_xor_sync(0xffffffffu, rs0, 2);
    rs1 += __shfl_xor_sync(0xffffffffu, rs1, 1);
    rs1 += __shfl_xor_sync(0xffffffffu, rs1, 2);
    const float inv0 = 1.f / rs0, inv1 = 1.f / rs1;

    const int g = lane >> 2, tq = lane & 3;
    const int row0 = q0 + wid * 16 + g;
#pragma unroll
    for (int nt = 0; nt < 8; ++nt) {
        int col = nt * 8 + tq * 2;
        u32 hp, lp;
        split_pack_h(oc[nt][0] * inv0, oc[nt][1] * inv0, hp, lp);
        *(u32*)(Oh_ + base + (size_t)row0 * DMODEL + col) = hp;
        *(u32*)(Ol_ + base + (size_t)row0 * DMODEL + col) = lp;
        split_pack_h(oc[nt][2] * inv1, oc[nt][3] * inv1, hp, lp);
        *(u32*)(Oh_ + base + (size_t)(row0 + 8) * DMODEL + col) = hp;
        *(u32*)(Ol_ + base + (size_t)(row0 + 8) * DMODEL + col) = lp;
    }
}

// ---------------------------------------------------------------------------
// Launch
// ---------------------------------------------------------------------------
extern "C" void kernel_launch(void* const* d_in, const int* in_sizes, int n_in,
                              void* d_out, int out_size)
{
    const float* query = (const float*)d_in[0];
    const float* key   = (const float*)d_in[1];
    const float* value = (const float*)d_in[2];
    const float* Wq = (const float*)d_in[3];
    const float* bq = (const float*)d_in[4];
    const float* Wk = (const float*)d_in[5];
    const float* bk = (const float*)d_in[6];
    const float* Wv = (const float*)d_in[7];
    const float* bv = (const float*)d_in[8];
    const float* Wo = (const float*)d_in[9];
    const float* bo = (const float*)d_in[10];
    float* out = (float*)d_out;

    half *act, *prjh, *obuf, *whbuf;
    cudaGetSymbolAddress((void**)&act,   g_act);
    cudaGetSymbolAddress((void**)&prjh,  g_prjh);
    cudaGetSymbolAddress((void**)&obuf,  g_o);
    cudaGetSymbolAddress((void**)&whbuf, g_wh);

    half *aq_h = act,          *aq_l = act + SZ;
    half *ak_h = act + 2 * SZ, *ak_l = act + 3 * SZ;
    half *av_h = act + 4 * SZ, *av_l = act + 5 * SZ;
    half *q_h = prjh, *k_h = prjh + SZ, *v_h = prjh + 2 * SZ;
    half *o_h = obuf, *o_l = obuf + SZ;
    half *wq_t = whbuf, *wk_t = whbuf + WSZ;
    half *wv_t = whbuf + 2 * WSZ, *wo_t = whbuf + 3 * WSZ;

    const int n4 = (int)(SZ / 4);
    conv_split_h<<<(n4 + 255) / 256, 256>>>(query, aq_h, aq_l, n4);
    conv_split_h<<<(n4 + 255) / 256, 256>>>(key,   ak_h, ak_l, n4);
    conv_split_h<<<(n4 + 255) / 256, 256>>>(value, av_h, av_l, n4);
    dim3 wtg(32, 32), wtb(32, 8);
    conv_wt_h<<<wtg, wtb>>>(Wq, wq_t);
    conv_wt_h<<<wtg, wtb>>>(Wk, wk_t);
    conv_wt_h<<<wtg, wtb>>>(Wv, wv_t);
    conv_wt_h<<<wtg, wtb>>>(Wo, wo_t);

    dim3 ggrid(DMODEL / 128, MROWS / 128);   // (8, 64)

    const int g2sm = 98304;   // 2 stages x 48 KB (occupancy 1 — no reg cap)
    cudaFuncSetAttribute(gemm2h, cudaFuncAttributeMaxDynamicSharedMemorySize, g2sm);
    gemm2h<<<ggrid, 256, g2sm>>>(aq_h, aq_l, wq_t, bq, q_h, nullptr);
    gemm2h<<<ggrid, 256, g2sm>>>(ak_h, ak_l, wk_t, bk, k_h, nullptr);
    gemm2h<<<ggrid, 256, g2sm>>>(av_h, av_l, wv_t, bv, v_h, nullptr);

    const int fsm = 49152;    // Q 16 KB + 2 stages x 16 KB -> 2 CTAs/SM
    cudaFuncSetAttribute(flash_h, cudaFuncAttributeMaxDynamicSharedMemorySize, fsm);
    dim3 fgrid(SEQ / 128, NHEADS, BATCH);    // (16, 16, 4)
    flash_h<<<fgrid, 256, fsm>>>(q_h, k_h, v_h, o_h, o_l);

    // Final output GEMM: O (split-fp16) @ Wo (single fp16) -> fp32 out
    gemm2h<<<ggrid, 256, g2sm>>>(o_h, o_l, wo_t, bo, nullptr, out);
}